// round 12
// baseline (speedup 1.0000x reference)
#include <cuda_runtime.h>
#include <cuda_fp16.h>

#define D      4096
#define R      16
#define NS     192
#define LB     1280
#define TPB    512
#define CH     8
#define SLOTS  5                      // chunk slots per adapter (m <= 40)
#define IPT    3                      // ceil(1280/512)

typedef unsigned long long ull;
union U8 { uint4 u; __half2 h2[4]; __half h[8]; };

// ---- device scratch ----
__device__ uint4 g_y4[(size_t)1024 * (D / 8)];  // fp16 y, summed-segment rows only

// smem layout (dynamic)
#define SM_XH    0                              // uint4 [4096] = 64 KB (8 rows fp16, d-major)
#define SM_RED   65536                          // ull [16][4][16] = 8 KB
#define SM_HS    (65536 + 8192)                 // ull [64]
#define SM_ROW   (65536 + 8192 + 512)           // int shrow[8], shxid[8]
#define SM_SCAN  (65536 + 8192 + 512 + 64)      // int swarp[16], stot, slist[64]
#define SM_SZ    (65536 + 8192 + 512 + 64 + 384)

// ---- packed f32x2 helpers (sm_100+) ----
__device__ __forceinline__ ull pk2(float lo, float hi) {
    ull r; asm("mov.b64 %0, {%1, %2};" : "=l"(r) : "f"(lo), "f"(hi)); return r;
}
__device__ __forceinline__ void up2(ull v, float& lo, float& hi) {
    asm("mov.b64 {%0, %1}, %2;" : "=f"(lo), "=f"(hi) : "l"(v));
}
__device__ __forceinline__ ull ffma2(ull a, ull b, ull c) {
    ull d; asm("fma.rn.f32x2 %0, %1, %2, %3;" : "=l"(d) : "l"(a), "l"(b), "l"(c)); return d;
}
__device__ __forceinline__ ull fadd2(ull a, ull b) {
    ull d; asm("add.rn.f32x2 %0, %1, %2;" : "=l"(d) : "l"(a), "l"(b)); return d;
}

// ---------------------------------------------------------------- compute
__global__ void __launch_bounds__(TPB, 2) k_compute(
    const float* __restrict__ x,
    const float* __restrict__ lA,
    const float* __restrict__ lB,
    const int*   __restrict__ xids,
    const int*   __restrict__ wids,
    float*       __restrict__ out)
{
    int w    = blockIdx.x / SLOTS;
    int slot = blockIdx.x % SLOTS;

    extern __shared__ char smem[];
    uint4* xh    = (uint4*)(smem + SM_XH);
    ull*   red   = (ull*)(smem + SM_RED);
    ull*   hsf   = (ull*)(smem + SM_HS);
    int*   shrow = (int*)(smem + SM_ROW);
    int*   shxid = shrow + 8;
    int*   swarp = (int*)(smem + SM_SCAN);
    int*   stot  = swarp + 16;
    int*   slist = stot + 1;

    int t = threadIdx.x, lane = t & 31, W = t >> 5;   // 16 warps

    // ---- in-block gather scan for adapter w (IPT=3, guarded) ----
    int base = t * IPT;
    int mt[IPT];
    int cnt = 0;
#pragma unroll
    for (int k = 0; k < IPT; k++) {
        int i = base + k;
        mt[k] = (i < LB && wids[i] == w) ? 1 : 0;
        cnt += mt[k];
    }
    int incl = cnt;
#pragma unroll
    for (int o = 1; o < 32; o <<= 1) {
        int v = __shfl_up_sync(0xffffffffu, incl, o);
        if (lane >= o) incl += v;
    }
    if (lane == 31) swarp[W] = incl;
    __syncthreads();
    if (t == 0) {
        int s = 0;
#pragma unroll
        for (int q = 0; q < 16; q++) { int v = swarp[q]; swarp[q] = s; s += v; }
        *stot = s;
    }
    __syncthreads();
    int m = *stot;
    if (slot * CH >= m) return;          // dead slot (uniform)
    int excl = incl - cnt + swarp[W];
#pragma unroll
    for (int k = 0; k < IPT; k++)
        if (mt[k]) slist[excl++] = base + k;
    __syncthreads();

    int nr = min(CH, m - slot * CH);
    if (t < CH) {
        int rr = (t < nr) ? slist[slot * CH + t] : -1;
        shrow[t] = rr;
        shxid[t] = (rr >= 0) ? xids[rr] : -1;
    }
    __syncthreads();

    // ---- stage x (lossless fp16: inputs are fp16 upcast to f32), d-major ----
    {
        int xid[8];
#pragma unroll
        for (int j = 0; j < 8; j++) xid[j] = shxid[j];
#pragma unroll
        for (int i = 0; i < 8; i++) {
            int d = t + i * TPB;
            float v[8];
#pragma unroll
            for (int j = 0; j < 8; j++)
                v[j] = (xid[j] >= 0) ? x[(size_t)xid[j] * D + d] : 0.0f;
            __half2 p0 = __floats2half2_rn(v[0], v[1]);
            __half2 p1 = __floats2half2_rn(v[2], v[3]);
            __half2 p2 = __floats2half2_rn(v[4], v[5]);
            __half2 p3 = __floats2half2_rn(v[6], v[7]);
            xh[d] = make_uint4(*(unsigned*)&p0, *(unsigned*)&p1,
                               *(unsigned*)&p2, *(unsigned*)&p3);
        }
    }
    __syncthreads();

    // ---- phase 1: h = x . A  (warp owns a 256-d stripe) ----
    const float* A = lA + (size_t)w * D * R;
    ull accp[4][4];
#pragma unroll
    for (int jp = 0; jp < 4; jp++)
#pragma unroll
        for (int k = 0; k < 4; k++) accp[jp][k] = 0ull;

    int dw = W * 256;
#pragma unroll 4
    for (int s = 0; s < 32; s++) {
        float4 a4 = ((const float4*)A)[(dw + s * 8) * 4 + lane];   // 512B/warp
        ull av0 = pk2(a4.x, a4.x), av1 = pk2(a4.y, a4.y);
        ull av2 = pk2(a4.z, a4.z), av3 = pk2(a4.w, a4.w);
        uint4 xq = xh[dw + s * 8 + (lane >> 2)];                   // LDS.128 bcast
        U8 xu; xu.u = xq;
#pragma unroll
        for (int jp = 0; jp < 4; jp++) {
            float2 xf = __half22float2(xu.h2[jp]);
            ull xp = pk2(xf.x, xf.y);
            accp[jp][0] = ffma2(xp, av0, accp[jp][0]);
            accp[jp][1] = ffma2(xp, av1, accp[jp][1]);
            accp[jp][2] = ffma2(xp, av2, accp[jp][2]);
            accp[jp][3] = ffma2(xp, av3, accp[jp][3]);
        }
    }

    // reduce across lanes sharing the same r-quad (lane bits 2..4)
#pragma unroll
    for (int mask = 4; mask <= 16; mask <<= 1)
#pragma unroll
        for (int jp = 0; jp < 4; jp++)
#pragma unroll
            for (int k = 0; k < 4; k++) {
                ull o = __shfl_xor_sync(0xffffffffu, accp[jp][k], mask);
                accp[jp][k] = fadd2(accp[jp][k], o);
            }
    if (lane < 4) {
#pragma unroll
        for (int jp = 0; jp < 4; jp++)
#pragma unroll
            for (int k = 0; k < 4; k++)
                red[(W * 4 + jp) * 16 + lane * 4 + k] = accp[jp][k];
    }
    __syncthreads();

    // cross-warp reduce (16 partials) + fp16-quantize h with x2 folded in
    if (t < 64) {
        int jp = t >> 4, r = t & 15;
        ull s = red[jp * 16 + r];
#pragma unroll
        for (int q = 1; q < 16; q++) s = fadd2(s, red[(q * 4 + jp) * 16 + r]);
        float lo, hi; up2(s, lo, hi);
        lo = __half2float(__float2half(2.0f * lo));
        hi = __half2float(__float2half(2.0f * hi));
        hsf[r * 4 + jp] = pk2(lo, hi);
    }
    __syncthreads();

    // ---- phase 2: y = (2h) . B  (coalesced; pass-through straight to out) ----
    const float* B = lB + (size_t)w * R * D;
#pragma unroll
    for (int c = 0; c < 2; c++) {
        int c4 = t + c * TPB;
#pragma unroll
        for (int jp = 0; jp < 4; jp++)
#pragma unroll
            for (int k = 0; k < 4; k++) accp[jp][k] = 0ull;
#pragma unroll 4
        for (int r = 0; r < 16; r++) {
            float4 b4 = ((const float4*)B)[r * (D / 4) + c4];
            ull bv0 = pk2(b4.x, b4.x), bv1 = pk2(b4.y, b4.y);
            ull bv2 = pk2(b4.z, b4.z), bv3 = pk2(b4.w, b4.w);
#pragma unroll
            for (int jp = 0; jp < 4; jp++) {
                ull hv = hsf[r * 4 + jp];                  // LDS.64 broadcast
                accp[jp][0] = ffma2(hv, bv0, accp[jp][0]);
                accp[jp][1] = ffma2(hv, bv1, accp[jp][1]);
                accp[jp][2] = ffma2(hv, bv2, accp[jp][2]);
                accp[jp][3] = ffma2(hv, bv3, accp[jp][3]);
            }
        }
#pragma unroll
        for (int jp = 0; jp < 4; jp++) {
            float l0, h0, l1, h1, l2, h2, l3, h3;
            up2(accp[jp][0], l0, h0); up2(accp[jp][1], l1, h1);
            up2(accp[jp][2], l2, h2); up2(accp[jp][3], l3, h3);
            int ra = shrow[2 * jp], rb = shrow[2 * jp + 1];
            if (ra >= 0) {
                __half2 q0 = __floats2half2_rn(l0, l1);
                __half2 q1 = __floats2half2_rn(l2, l3);
                if (ra < 1024) {
                    ((uint2*)((__half*)g_y4 + (size_t)ra * D))[c4] =
                        make_uint2(*(unsigned*)&q0, *(unsigned*)&q1);
                } else {            // pass-through: fp16-quantized, widened to f32
                    float2 f0 = __half22float2(q0), f1 = __half22float2(q1);
                    ((float4*)out)[(size_t)(ra - 768) * (D / 4) + c4] =
                        make_float4(f0.x, f0.y, f1.x, f1.y);
                }
            }
            if (rb >= 0) {
                __half2 q0 = __floats2half2_rn(h0, h1);
                __half2 q1 = __floats2half2_rn(h2, h3);
                if (rb < 1024) {
                    ((uint2*)((__half*)g_y4 + (size_t)rb * D))[c4] =
                        make_uint2(*(unsigned*)&q0, *(unsigned*)&q1);
                } else {
                    float2 f0 = __half22float2(q0), f1 = __half22float2(q1);
                    ((float4*)out)[(size_t)(rb - 768) * (D / 4) + c4] =
                        make_float4(f0.x, f0.y, f1.x, f1.y);
                }
            }
        }
    }
}

// ---------------------------------------------------------------- finalize
// R10's measured-best shape: 512 blocks x 256, one uint4 per thread, 256 segs
__global__ void k_final(float* __restrict__ out) {
    const int UPR = D / 8;
    int idx = blockIdx.x * blockDim.x + threadIdx.x;
    if (idx >= 256 * UPR) return;
    int o  = idx / UPR;
    int dv = idx % UPR;

    U8 a, b, c, d, rr;
    a.u = g_y4[(size_t)(4 * o + 0) * UPR + dv];
    b.u = g_y4[(size_t)(4 * o + 1) * UPR + dv];
    c.u = g_y4[(size_t)(4 * o + 2) * UPR + dv];
    d.u = g_y4[(size_t)(4 * o + 3) * UPR + dv];
#pragma unroll
    for (int k = 0; k < 4; k++)         // sequential fp16 adds, ascending index
        rr.h2[k] = __hadd2(__hadd2(__hadd2(a.h2[k], b.h2[k]), c.h2[k]), d.h2[k]);

    float4 f0, f1;
    f0.x = __half2float(rr.h[0]); f0.y = __half2float(rr.h[1]);
    f0.z = __half2float(rr.h[2]); f0.w = __half2float(rr.h[3]);
    f1.x = __half2float(rr.h[4]); f1.y = __half2float(rr.h[5]);
    f1.z = __half2float(rr.h[6]); f1.w = __half2float(rr.h[7]);
    ((float4*)out)[idx * 2]     = f0;
    ((float4*)out)[idx * 2 + 1] = f1;
}

// ---------------------------------------------------------------- launch
extern "C" void kernel_launch(void* const* d_in, const int* in_sizes, int n_in,
                              void* d_out, int out_size) {
    const float* x    = (const float*)d_in[0];
    const float* lA   = (const float*)d_in[1];
    const float* lB   = (const float*)d_in[2];
    const int*   xids = (const int*)d_in[3];
    const int*   wids = (const int*)d_in[4];
    float*       out  = (float*)d_out;

    cudaFuncSetAttribute(k_compute,
                         cudaFuncAttributeMaxDynamicSharedMemorySize, SM_SZ);

    k_compute<<<NS * SLOTS, TPB, SM_SZ>>>(x, lA, lB, xids, wids, out);
    k_final<<<512, 256>>>(out);
}

// round 13
// speedup vs baseline: 1.5304x; 1.5304x over previous
#include <cuda_runtime.h>
#include <cuda_fp16.h>

#define D      4096
#define R      16
#define NS     192
#define LB     1280
#define TPB    256
#define CH     8
#define SLOTS  5                      // chunk slots per adapter (m <= 40)
#define IPT    (LB / TPB)             // 5

typedef unsigned long long ull;
union U8 { uint4 u; __half2 h2[4]; __half h[8]; };

// ---- device scratch ----
__device__ uint4 g_y4[(size_t)1024 * (D / 8)];  // fp16 y, summed-segment rows only

// smem layout (dynamic)
#define SM_XH    0                             // uint4 [4096] (d-major, 8 rows fp16) = 64 KB
#define SM_RED   65536                         // ull [8][4][16] = 4 KB
#define SM_HS    (65536 + 4096)                // ull [64]
#define SM_ROW   (65536 + 4096 + 512)          // int shrow[8], shxid[8]
#define SM_SCAN  (65536 + 4096 + 512 + 64)     // int swarp[8], stot, slist[64]
#define SM_SZ    (65536 + 4096 + 512 + 64 + 512)

// ---- packed f32x2 helpers (sm_100+) ----
__device__ __forceinline__ ull pk2(float lo, float hi) {
    ull r; asm("mov.b64 %0, {%1, %2};" : "=l"(r) : "f"(lo), "f"(hi)); return r;
}
__device__ __forceinline__ void up2(ull v, float& lo, float& hi) {
    asm("mov.b64 {%0, %1}, %2;" : "=f"(lo), "=f"(hi) : "l"(v));
}
__device__ __forceinline__ ull ffma2(ull a, ull b, ull c) {
    ull d; asm("fma.rn.f32x2 %0, %1, %2, %3;" : "=l"(d) : "l"(a), "l"(b), "l"(c)); return d;
}
__device__ __forceinline__ ull fadd2(ull a, ull b) {
    ull d; asm("add.rn.f32x2 %0, %1, %2;" : "=l"(d) : "l"(a), "l"(b)); return d;
}

// ---------------------------------------------------------------- compute
__global__ void __launch_bounds__(TPB, 2) k_compute(
    const float* __restrict__ x,
    const float* __restrict__ lA,
    const float* __restrict__ lB,
    const int*   __restrict__ xids,
    const int*   __restrict__ wids,
    float*       __restrict__ out)
{
    int w    = blockIdx.x / SLOTS;
    int slot = blockIdx.x % SLOTS;

    extern __shared__ char smem[];
    uint4* xh    = (uint4*)(smem + SM_XH);
    ull*   red   = (ull*)(smem + SM_RED);
    ull*   hsf   = (ull*)(smem + SM_HS);
    int*   shrow = (int*)(smem + SM_ROW);
    int*   shxid = shrow + 8;
    int*   swarp = (int*)(smem + SM_SCAN);
    int*   stot  = swarp + 8;
    int*   slist = stot + 1;

    int t = threadIdx.x, lane = t & 31, W = t >> 5;

    // ---- in-block gather scan for adapter w ----
    int base = t * IPT;
    int mt[IPT];
    int cnt = 0;
#pragma unroll
    for (int k = 0; k < IPT; k++) {
        mt[k] = (wids[base + k] == w) ? 1 : 0;
        cnt += mt[k];
    }
    int incl = cnt;
#pragma unroll
    for (int o = 1; o < 32; o <<= 1) {
        int v = __shfl_up_sync(0xffffffffu, incl, o);
        if (lane >= o) incl += v;
    }
    if (lane == 31) swarp[W] = incl;
    __syncthreads();
    if (t == 0) {
        int s = 0;
#pragma unroll
        for (int q = 0; q < 8; q++) { int v = swarp[q]; swarp[q] = s; s += v; }
        *stot = s;
    }
    __syncthreads();
    int m = *stot;
    if (slot * CH >= m) return;          // dead slot (uniform)
    int excl = incl - cnt + swarp[W];
#pragma unroll
    for (int k = 0; k < IPT; k++)
        if (mt[k]) slist[excl++] = base + k;
    __syncthreads();

    int nr = min(CH, m - slot * CH);
    if (t < CH) {
        int rr = (t < nr) ? slist[slot * CH + t] : -1;
        shrow[t] = rr;
        shxid[t] = (rr >= 0) ? xids[rr] : -1;
    }
    __syncthreads();

    // ---- stage x (lossless fp16: inputs are fp16 upcast to f32), d-major ----
    {
        int xid[8];
#pragma unroll
        for (int j = 0; j < 8; j++) xid[j] = shxid[j];
#pragma unroll
        for (int i = 0; i < 16; i++) {
            int d = t + i * TPB;
            float v[8];
#pragma unroll
            for (int j = 0; j < 8; j++)
                v[j] = (xid[j] >= 0) ? x[(size_t)xid[j] * D + d] : 0.0f;
            __half2 p0 = __floats2half2_rn(v[0], v[1]);
            __half2 p1 = __floats2half2_rn(v[2], v[3]);
            __half2 p2 = __floats2half2_rn(v[4], v[5]);
            __half2 p3 = __floats2half2_rn(v[6], v[7]);
            xh[d] = make_uint4(*(unsigned*)&p0, *(unsigned*)&p1,
                               *(unsigned*)&p2, *(unsigned*)&p3);
        }
    }
    __syncthreads();

    // ---- phase 1: h = x . A  (warp owns a 512-d stripe; unroll 8 -> MLP 8) ----
    const float* A = lA + (size_t)w * D * R;
    ull accp[4][4];
#pragma unroll
    for (int jp = 0; jp < 4; jp++)
#pragma unroll
        for (int k = 0; k < 4; k++) accp[jp][k] = 0ull;

    int dw = W * 512;
#pragma unroll 8
    for (int s = 0; s < 64; s++) {
        float4 a4 = ((const float4*)A)[(dw + s * 8) * 4 + lane];   // 512B/warp
        ull av0 = pk2(a4.x, a4.x), av1 = pk2(a4.y, a4.y);
        ull av2 = pk2(a4.z, a4.z), av3 = pk2(a4.w, a4.w);
        uint4 xq = xh[dw + s * 8 + (lane >> 2)];                   // LDS.128 bcast
        U8 xu; xu.u = xq;
#pragma unroll
        for (int jp = 0; jp < 4; jp++) {
            float2 xf = __half22float2(xu.h2[jp]);
            ull xp = pk2(xf.x, xf.y);
            accp[jp][0] = ffma2(xp, av0, accp[jp][0]);
            accp[jp][1] = ffma2(xp, av1, accp[jp][1]);
            accp[jp][2] = ffma2(xp, av2, accp[jp][2]);
            accp[jp][3] = ffma2(xp, av3, accp[jp][3]);
        }
    }

    // reduce across lanes sharing the same r-quad (lane bits 2..4)
#pragma unroll
    for (int mask = 4; mask <= 16; mask <<= 1)
#pragma unroll
        for (int jp = 0; jp < 4; jp++)
#pragma unroll
            for (int k = 0; k < 4; k++) {
                ull o = __shfl_xor_sync(0xffffffffu, accp[jp][k], mask);
                accp[jp][k] = fadd2(accp[jp][k], o);
            }
    if (lane < 4) {
#pragma unroll
        for (int jp = 0; jp < 4; jp++)
#pragma unroll
            for (int k = 0; k < 4; k++)
                red[(W * 4 + jp) * 16 + lane * 4 + k] = accp[jp][k];
    }
    __syncthreads();

    // cross-warp reduce + fp16-quantize h with x2 folded in (exact scale)
    if (t < 64) {
        int jp = t >> 4, r = t & 15;
        ull s = red[jp * 16 + r];
#pragma unroll
        for (int q = 1; q < 8; q++) s = fadd2(s, red[(q * 4 + jp) * 16 + r]);
        float lo, hi; up2(s, lo, hi);
        lo = __half2float(__float2half(2.0f * lo));
        hi = __half2float(__float2half(2.0f * hi));
        hsf[r * 4 + jp] = pk2(lo, hi);
    }
    __syncthreads();

    // ---- phase 2: y = (2h) . B  (unroll 8; pass-through straight to out) ----
    const float* B = lB + (size_t)w * R * D;
#pragma unroll
    for (int c = 0; c < 4; c++) {
        int c4 = t + c * TPB;
#pragma unroll
        for (int jp = 0; jp < 4; jp++)
#pragma unroll
            for (int k = 0; k < 4; k++) accp[jp][k] = 0ull;
#pragma unroll 8
        for (int r = 0; r < 16; r++) {
            float4 b4 = ((const float4*)B)[r * (D / 4) + c4];
            ull bv0 = pk2(b4.x, b4.x), bv1 = pk2(b4.y, b4.y);
            ull bv2 = pk2(b4.z, b4.z), bv3 = pk2(b4.w, b4.w);
#pragma unroll
            for (int jp = 0; jp < 4; jp++) {
                ull hv = hsf[r * 4 + jp];                  // LDS.64 broadcast
                accp[jp][0] = ffma2(hv, bv0, accp[jp][0]);
                accp[jp][1] = ffma2(hv, bv1, accp[jp][1]);
                accp[jp][2] = ffma2(hv, bv2, accp[jp][2]);
                accp[jp][3] = ffma2(hv, bv3, accp[jp][3]);
            }
        }
#pragma unroll
        for (int jp = 0; jp < 4; jp++) {
            float l0, h0, l1, h1, l2, h2, l3, h3;
            up2(accp[jp][0], l0, h0); up2(accp[jp][1], l1, h1);
            up2(accp[jp][2], l2, h2); up2(accp[jp][3], l3, h3);
            int ra = shrow[2 * jp], rb = shrow[2 * jp + 1];
            if (ra >= 0) {
                __half2 q0 = __floats2half2_rn(l0, l1);
                __half2 q1 = __floats2half2_rn(l2, l3);
                if (ra < 1024) {
                    ((uint2*)((__half*)g_y4 + (size_t)ra * D))[c4] =
                        make_uint2(*(unsigned*)&q0, *(unsigned*)&q1);
                } else {            // pass-through: fp16-quantized, widened to f32
                    float2 f0 = __half22float2(q0), f1 = __half22float2(q1);
                    ((float4*)out)[(size_t)(ra - 768) * (D / 4) + c4] =
                        make_float4(f0.x, f0.y, f1.x, f1.y);
                }
            }
            if (rb >= 0) {
                __half2 q0 = __floats2half2_rn(h0, h1);
                __half2 q1 = __floats2half2_rn(h2, h3);
                if (rb < 1024) {
                    ((uint2*)((__half*)g_y4 + (size_t)rb * D))[c4] =
                        make_uint2(*(unsigned*)&q0, *(unsigned*)&q1);
                } else {
                    float2 f0 = __half22float2(q0), f1 = __half22float2(q1);
                    ((float4*)out)[(size_t)(rb - 768) * (D / 4) + c4] =
                        make_float4(f0.x, f0.y, f1.x, f1.y);
                }
            }
        }
    }
}

// ---------------------------------------------------------------- finalize
// R10's measured-best shape: 512 blocks x 256, one uint4 per thread, 256 segs
__global__ void k_final(float* __restrict__ out) {
    const int UPR = D / 8;
    int idx = blockIdx.x * blockDim.x + threadIdx.x;
    if (idx >= 256 * UPR) return;
    int o  = idx / UPR;
    int dv = idx % UPR;

    U8 a, b, c, d, rr;
    a.u = g_y4[(size_t)(4 * o + 0) * UPR + dv];
    b.u = g_y4[(size_t)(4 * o + 1) * UPR + dv];
    c.u = g_y4[(size_t)(4 * o + 2) * UPR + dv];
    d.u = g_y4[(size_t)(4 * o + 3) * UPR + dv];
#pragma unroll
    for (int k = 0; k < 4; k++)         // sequential fp16 adds, ascending index
        rr.h2[k] = __hadd2(__hadd2(__hadd2(a.h2[k], b.h2[k]), c.h2[k]), d.h2[k]);

    float4 f0, f1;
    f0.x = __half2float(rr.h[0]); f0.y = __half2float(rr.h[1]);
    f0.z = __half2float(rr.h[2]); f0.w = __half2float(rr.h[3]);
    f1.x = __half2float(rr.h[4]); f1.y = __half2float(rr.h[5]);
    f1.z = __half2float(rr.h[6]); f1.w = __half2float(rr.h[7]);
    ((float4*)out)[idx * 2]     = f0;
    ((float4*)out)[idx * 2 + 1] = f1;
}

// ---------------------------------------------------------------- launch
extern "C" void kernel_launch(void* const* d_in, const int* in_sizes, int n_in,
                              void* d_out, int out_size) {
    const float* x    = (const float*)d_in[0];
    const float* lA   = (const float*)d_in[1];
    const float* lB   = (const float*)d_in[2];
    const int*   xids = (const int*)d_in[3];
    const int*   wids = (const int*)d_in[4];
    float*       out  = (float*)d_out;

    cudaFuncSetAttribute(k_compute,
                         cudaFuncAttributeMaxDynamicSharedMemorySize, SM_SZ);

    k_compute<<<NS * SLOTS, TPB, SM_SZ>>>(x, lA, lB, xids, wids, out);
    k_final<<<512, 256>>>(out);
}